// round 1
// baseline (speedup 1.0000x reference)
#include <cuda_runtime.h>
#include <math.h>

#define F    1024
#define NJ   64
#define C    256
#define HID  1024
#define H    8
#define D    128
#define M_TOT (NJ * F)      // 65536
#define EPSV 1e-6f

// Scratch (device globals — no allocation allowed in kernel_launch)
__device__ float g_Q[(size_t)M_TOT * HID];   // feature-mapped Q  (n, f, hid)
__device__ float g_K[(size_t)M_TOT * HID];   // feature-mapped K
__device__ float g_V[(size_t)M_TOT * HID];   // V
__device__ float g_KV[(size_t)NJ * H * D * D];   // KV[n,h,m,d]
__device__ float g_Ksum[(size_t)NJ * H * D];     // Ksum[n,h,d]

// ---------------------------------------------------------------------------
// Kernel 1: fused QKV projection + bias + feature map (elu(x)+1 for Q,K)
// A = x^T view: row m = n*F + f  -> x[f, n, :]   (M=65536, K=C=256)
// B = concat(Wq,Wk,Wv) columns (N=3072), block col range picks which W.
// 128x128 tile, BK=8, 256 threads, 8x8 per thread (split 4+4 halves).
// ---------------------------------------------------------------------------
__global__ __launch_bounds__(256) void qkv_kernel(
    const float* __restrict__ x,
    const float* __restrict__ Wq, const float* __restrict__ bq,
    const float* __restrict__ Wk, const float* __restrict__ bk,
    const float* __restrict__ Wv, const float* __restrict__ bv)
{
    __shared__ float As[8][128];
    __shared__ float Bs[8][128];

    const int tid = threadIdx.x;
    const int bm  = blockIdx.x;       // 0..511
    const int bn  = blockIdx.y;       // 0..23
    const int w   = bn >> 3;          // 0=Q,1=K,2=V
    const float* Wp   = (w == 0) ? Wq : ((w == 1) ? Wk : Wv);
    const float* bias = (w == 0) ? bq : ((w == 1) ? bk : bv);
    float* OUT        = (w == 0) ? g_Q : ((w == 1) ? g_K : g_V);
    const int colbase = (bn & 7) * 128;

    // A loader: row ar (0..127), 4 k-values
    const int ar = tid >> 1;
    const int ak = (tid & 1) * 4;
    const int am = bm * 128 + ar;           // m = n*F + f
    const int fidx = am & (F - 1);
    const int nidx = am >> 10;
    const float* aptr = x + (size_t)fidx * (NJ * C) + (size_t)nidx * C + ak;

    // B loader: k-row bkr (0..7), 4 columns
    const int bkr = tid >> 5;
    const int bc  = (tid & 31) * 4;
    const float* bptr = Wp + (size_t)bkr * HID + colbase + bc;

    const int ty = tid >> 4, tx = tid & 15;

    float acc[8][8];
#pragma unroll
    for (int i = 0; i < 8; i++)
#pragma unroll
        for (int j = 0; j < 8; j++) acc[i][j] = 0.f;

    for (int k0 = 0; k0 < C; k0 += 8) {
        float4 a = *(const float4*)(aptr + k0);
        float4 b = *(const float4*)(bptr + (size_t)k0 * HID);
        __syncthreads();
        As[ak + 0][ar] = a.x; As[ak + 1][ar] = a.y;
        As[ak + 2][ar] = a.z; As[ak + 3][ar] = a.w;
        *(float4*)&Bs[bkr][bc] = b;
        __syncthreads();
#pragma unroll
        for (int kk = 0; kk < 8; kk++) {
            float4 a0 = *(const float4*)&As[kk][ty * 4];
            float4 a1 = *(const float4*)&As[kk][64 + ty * 4];
            float4 b0 = *(const float4*)&Bs[kk][tx * 4];
            float4 b1 = *(const float4*)&Bs[kk][64 + tx * 4];
            float ra[8] = {a0.x, a0.y, a0.z, a0.w, a1.x, a1.y, a1.z, a1.w};
            float rb[8] = {b0.x, b0.y, b0.z, b0.w, b1.x, b1.y, b1.z, b1.w};
#pragma unroll
            for (int i = 0; i < 8; i++)
#pragma unroll
                for (int j = 0; j < 8; j++) acc[i][j] += ra[i] * rb[j];
        }
    }

    const bool fmap = (w < 2);
    float4 bi0 = *(const float4*)(bias + colbase + tx * 4);
    float4 bi1 = *(const float4*)(bias + colbase + 64 + tx * 4);
    float bb[8] = {bi0.x, bi0.y, bi0.z, bi0.w, bi1.x, bi1.y, bi1.z, bi1.w};

#pragma unroll
    for (int i = 0; i < 8; i++) {
        int r = (i < 4) ? (ty * 4 + i) : (64 + ty * 4 + (i - 4));
        size_t obase = (size_t)(bm * 128 + r) * HID + colbase;
        float vv[8];
#pragma unroll
        for (int j = 0; j < 8; j++) {
            float v = acc[i][j] + bb[j];
            if (fmap) v = (v > 0.f) ? (v + 1.f) : __expf(v);
            vv[j] = v;
        }
        *(float4*)&OUT[obase + tx * 4]      = make_float4(vv[0], vv[1], vv[2], vv[3]);
        *(float4*)&OUT[obase + 64 + tx * 4] = make_float4(vv[4], vv[5], vv[6], vv[7]);
    }
}

// ---------------------------------------------------------------------------
// Kernel 2: KV[n,h,m,d] = sum_s V[n,s,h,m] * K[n,s,h,d]  (+ Ksum[n,h,d])
// One block per (n,h); 128x128 output, reduce over s=1024 in BK=8 tiles.
// ---------------------------------------------------------------------------
__global__ __launch_bounds__(256) void kv_kernel()
{
    __shared__ float Vs[8][128];
    __shared__ float Ks[8][128];
    __shared__ float sKsum[128];

    const int tid = threadIdx.x;
    const int n = blockIdx.x, h = blockIdx.y;
    const size_t base = (size_t)n * F * HID + (size_t)h * D;

    const int sr = tid >> 5;          // s within tile (0..7)
    const int c4 = (tid & 31) * 4;    // column
    const float* vptr = g_V + base + (size_t)sr * HID + c4;
    const float* kptr = g_K + base + (size_t)sr * HID + c4;

    if (tid < 128) sKsum[tid] = 0.f;
    float ks[4] = {0.f, 0.f, 0.f, 0.f};

    const int ty = tid >> 4, tx = tid & 15;
    float acc[8][8];
#pragma unroll
    for (int i = 0; i < 8; i++)
#pragma unroll
        for (int j = 0; j < 8; j++) acc[i][j] = 0.f;

    for (int s0 = 0; s0 < F; s0 += 8) {
        float4 av = *(const float4*)(vptr + (size_t)s0 * HID);
        float4 bk = *(const float4*)(kptr + (size_t)s0 * HID);
        __syncthreads();
        *(float4*)&Vs[sr][c4] = av;
        *(float4*)&Ks[sr][c4] = bk;
        ks[0] += bk.x; ks[1] += bk.y; ks[2] += bk.z; ks[3] += bk.w;
        __syncthreads();
#pragma unroll
        for (int kk = 0; kk < 8; kk++) {
            float4 a0 = *(const float4*)&Vs[kk][ty * 4];
            float4 a1 = *(const float4*)&Vs[kk][64 + ty * 4];
            float4 b0 = *(const float4*)&Ks[kk][tx * 4];
            float4 b1 = *(const float4*)&Ks[kk][64 + tx * 4];
            float ra[8] = {a0.x, a0.y, a0.z, a0.w, a1.x, a1.y, a1.z, a1.w};
            float rb[8] = {b0.x, b0.y, b0.z, b0.w, b1.x, b1.y, b1.z, b1.w};
#pragma unroll
            for (int i = 0; i < 8; i++)
#pragma unroll
                for (int j = 0; j < 8; j++) acc[i][j] += ra[i] * rb[j];
        }
    }

    atomicAdd(&sKsum[c4 + 0], ks[0]);
    atomicAdd(&sKsum[c4 + 1], ks[1]);
    atomicAdd(&sKsum[c4 + 2], ks[2]);
    atomicAdd(&sKsum[c4 + 3], ks[3]);
    __syncthreads();

    const size_t nh = (size_t)n * H + h;
    if (tid < 128) g_Ksum[nh * D + tid] = sKsum[tid];

    const size_t kvbase = nh * D * D;
#pragma unroll
    for (int i = 0; i < 8; i++) {
        int r = (i < 4) ? (ty * 4 + i) : (64 + ty * 4 + (i - 4));   // m
        *(float4*)&g_KV[kvbase + (size_t)r * D + tx * 4] =
            make_float4(acc[i][0], acc[i][1], acc[i][2], acc[i][3]);
        *(float4*)&g_KV[kvbase + (size_t)r * D + 64 + tx * 4] =
            make_float4(acc[i][4], acc[i][5], acc[i][6], acc[i][7]);
    }
}

// ---------------------------------------------------------------------------
// Kernel 3: out[f, n, h*D+m] = Z[n,l,h] * sum_d Q[n,l,h,d] * KV[n,h,m,d]
// Z = 1/(Q . Ksum + eps). Block = (l-tile of 128) x (all 128 m), per (n,h).
// ---------------------------------------------------------------------------
__global__ __launch_bounds__(256) void out_kernel(float* __restrict__ out)
{
    __shared__ float Qs[8][128];
    __shared__ float KVs[8][128];
    __shared__ float sZ[128];
    __shared__ float sKs[128];

    const int tid = threadIdx.x;
    const int lt = blockIdx.x, n = blockIdx.y, h = blockIdx.z;
    const int l0 = lt * 128;
    const size_t nh = (size_t)n * H + h;
    const size_t qbase  = ((size_t)n * F + l0) * HID + (size_t)h * D;
    const size_t kvbase = nh * D * D;

    if (tid < 128) sKs[tid] = g_Ksum[nh * D + tid];
    __syncthreads();
    if (tid < 128) {
        const float* q = g_Q + qbase + (size_t)tid * HID;
        float dot = 0.f;
#pragma unroll 4
        for (int d = 0; d < D; d++) dot += q[d] * sKs[d];
        sZ[tid] = 1.f / (dot + EPSV);
    }

    const int lr  = tid >> 1;
    const int d4  = (tid & 1) * 4;
    const float* qptr  = g_Q + qbase + (size_t)lr * HID + d4;
    const float* kvptr = g_KV + kvbase + (size_t)lr * D + d4;

    const int ty = tid >> 4, tx = tid & 15;
    float acc[8][8];
#pragma unroll
    for (int i = 0; i < 8; i++)
#pragma unroll
        for (int j = 0; j < 8; j++) acc[i][j] = 0.f;

    for (int d0 = 0; d0 < D; d0 += 8) {
        float4 a = *(const float4*)(qptr + d0);
        float4 b = *(const float4*)(kvptr + d0);
        __syncthreads();
        Qs[d4 + 0][lr] = a.x; Qs[d4 + 1][lr] = a.y;
        Qs[d4 + 2][lr] = a.z; Qs[d4 + 3][lr] = a.w;
        KVs[d4 + 0][lr] = b.x; KVs[d4 + 1][lr] = b.y;
        KVs[d4 + 2][lr] = b.z; KVs[d4 + 3][lr] = b.w;
        __syncthreads();
#pragma unroll
        for (int kk = 0; kk < 8; kk++) {
            float4 a0 = *(const float4*)&Qs[kk][ty * 4];
            float4 a1 = *(const float4*)&Qs[kk][64 + ty * 4];
            float4 b0 = *(const float4*)&KVs[kk][tx * 4];
            float4 b1 = *(const float4*)&KVs[kk][64 + tx * 4];
            float ra[8] = {a0.x, a0.y, a0.z, a0.w, a1.x, a1.y, a1.z, a1.w};
            float rb[8] = {b0.x, b0.y, b0.z, b0.w, b1.x, b1.y, b1.z, b1.w};
#pragma unroll
            for (int i = 0; i < 8; i++)
#pragma unroll
                for (int j = 0; j < 8; j++) acc[i][j] += ra[i] * rb[j];
        }
    }

#pragma unroll
    for (int i = 0; i < 8; i++) {
        int r = (i < 4) ? (ty * 4 + i) : (64 + ty * 4 + (i - 4));   // l within tile
        float z = sZ[r];
        size_t obase = (size_t)(l0 + r) * (NJ * HID) + (size_t)n * HID + (size_t)h * D;
        *(float4*)&out[obase + tx * 4] =
            make_float4(acc[i][0] * z, acc[i][1] * z, acc[i][2] * z, acc[i][3] * z);
        *(float4*)&out[obase + 64 + tx * 4] =
            make_float4(acc[i][4] * z, acc[i][5] * z, acc[i][6] * z, acc[i][7] * z);
    }
}

// ---------------------------------------------------------------------------
extern "C" void kernel_launch(void* const* d_in, const int* in_sizes, int n_in,
                              void* d_out, int out_size)
{
    const float* x  = (const float*)d_in[0];
    const float* Wq = (const float*)d_in[1];
    const float* bq = (const float*)d_in[2];
    const float* Wk = (const float*)d_in[3];
    const float* bk = (const float*)d_in[4];
    const float* Wv = (const float*)d_in[5];
    const float* bv = (const float*)d_in[6];
    float* out = (float*)d_out;

    dim3 g1(M_TOT / 128, 24);            // 512 x 24
    qkv_kernel<<<g1, 256>>>(x, Wq, bq, Wk, bk, Wv, bv);

    dim3 g2(NJ, H);                      // 64 x 8
    kv_kernel<<<g2, 256>>>();

    dim3 g3(F / 128, NJ, H);             // 8 x 64 x 8
    out_kernel<<<g3, 256>>>(out);
}

// round 2
// speedup vs baseline: 1.6764x; 1.6764x over previous
#include <cuda_runtime.h>
#include <math.h>
#include <stdint.h>

#define F    1024
#define NJ   64
#define C    256
#define HID  1024
#define H    8
#define D    128
#define M_TOT (NJ * F)      // 65536
#define EPSV 1e-6f

// Scratch (device globals — no allocation allowed in kernel_launch)
__device__ float g_Q[(size_t)M_TOT * HID];   // feature-mapped Q  (n, f, hid)
__device__ float g_K[(size_t)M_TOT * HID];   // feature-mapped K
__device__ float g_V[(size_t)M_TOT * HID];   // V
__device__ float g_KV[(size_t)NJ * H * D * D];   // KV[n,h,m,d]
__device__ float g_Ksum[(size_t)NJ * H * D];     // Ksum[n,h,d]

__device__ __forceinline__ float ftf32(float x) {
    float r;
    asm("cvt.rna.tf32.f32 %0, %1;" : "=f"(r) : "f"(x));
    return r;
}

__device__ __forceinline__ void mma_tf32(float* c, const uint32_t* a,
                                         uint32_t b0, uint32_t b1) {
    asm volatile(
        "mma.sync.aligned.m16n8k8.row.col.f32.tf32.tf32.f32 "
        "{%0,%1,%2,%3}, {%4,%5,%6,%7}, {%8,%9}, {%0,%1,%2,%3};"
        : "+f"(c[0]), "+f"(c[1]), "+f"(c[2]), "+f"(c[3])
        : "r"(a[0]), "r"(a[1]), "r"(a[2]), "r"(a[3]), "r"(b0), "r"(b1));
}

// ---------------------------------------------------------------------------
// Kernel 1: fused QKV projection on tensor cores (tf32 mma.sync)
// A = x^T view (M=65536, K=256), B = one of Wq/Wk/Wv column block (N=3072).
// Block tile 128x128, BK=32, 256 threads (8 warps, 4x2), warp tile 32x64.
// Epilogue: +bias, elu(x)+1 for Q,K.
// ---------------------------------------------------------------------------
__global__ __launch_bounds__(256) void qkv_mma_kernel(
    const float* __restrict__ x,
    const float* __restrict__ Wq, const float* __restrict__ bq,
    const float* __restrict__ Wk, const float* __restrict__ bk,
    const float* __restrict__ Wv, const float* __restrict__ bv)
{
    __shared__ float As[32][136];   // [k][m]
    __shared__ float Bs[32][136];   // [k][n]

    const int tid  = threadIdx.x;
    const int lane = tid & 31;
    const int warp = tid >> 5;
    const int wm   = warp & 3;      // 0..3 -> m offset wm*32
    const int wn   = warp >> 2;     // 0..1 -> n offset wn*64
    const int gr   = lane >> 2;     // 0..7
    const int gc   = lane & 3;      // 0..3

    const int bm = blockIdx.x;      // 0..511
    const int bn = blockIdx.y;      // 0..23
    const int w  = bn >> 3;         // 0=Q,1=K,2=V
    const float* Wp   = (w == 0) ? Wq : ((w == 1) ? Wk : Wv);
    const float* bias = (w == 0) ? bq : ((w == 1) ? bk : bv);
    float* OUT        = (w == 0) ? g_Q : ((w == 1) ? g_K : g_V);
    const int colbase = (bn & 7) * 128;

    // A loader: row ar (0..127), two threads per row, 16 k each
    const int ar   = tid >> 1;
    const int am   = bm * 128 + ar;          // m = n*F + f
    const int fidx = am & (F - 1);
    const int nidx = am >> 10;
    const float* aptr = x + (size_t)fidx * (NJ * C) + (size_t)nidx * C + (tid & 1) * 16;

    // B loader: k-row bkr (0..31), 4 float4 per thread
    const int bkr = tid >> 3;
    const int bco = (tid & 7) * 4;
    const float* bptr = Wp + (size_t)bkr * HID + colbase + bco;

    float acc[2][8][4];
#pragma unroll
    for (int mf = 0; mf < 2; mf++)
#pragma unroll
        for (int nf = 0; nf < 8; nf++)
#pragma unroll
            for (int i = 0; i < 4; i++) acc[mf][nf][i] = 0.f;

    for (int kt = 0; kt < 8; kt++) {
        const int k0 = kt * 32;
        float4 aR[4], bR[4];
#pragma unroll
        for (int i = 0; i < 4; i++) aR[i] = *(const float4*)(aptr + k0 + i * 4);
#pragma unroll
        for (int i = 0; i < 4; i++) bR[i] = *(const float4*)(bptr + (size_t)k0 * HID + i * 32);

        __syncthreads();
#pragma unroll
        for (int i = 0; i < 4; i++) {
            const int kb = (tid & 1) * 16 + i * 4;
            As[kb + 0][ar] = ftf32(aR[i].x);
            As[kb + 1][ar] = ftf32(aR[i].y);
            As[kb + 2][ar] = ftf32(aR[i].z);
            As[kb + 3][ar] = ftf32(aR[i].w);
        }
#pragma unroll
        for (int i = 0; i < 4; i++) {
            float4 t = bR[i];
            t.x = ftf32(t.x); t.y = ftf32(t.y); t.z = ftf32(t.z); t.w = ftf32(t.w);
            *(float4*)&Bs[bkr][bco + i * 32] = t;
        }
        __syncthreads();

#pragma unroll
        for (int ks = 0; ks < 4; ks++) {
            const int kk = ks * 8;
            uint32_t afr[2][4];
#pragma unroll
            for (int mf = 0; mf < 2; mf++) {
                const int m0 = wm * 32 + mf * 16;
                afr[mf][0] = __float_as_uint(As[kk + gc][m0 + gr]);
                afr[mf][1] = __float_as_uint(As[kk + gc][m0 + gr + 8]);
                afr[mf][2] = __float_as_uint(As[kk + gc + 4][m0 + gr]);
                afr[mf][3] = __float_as_uint(As[kk + gc + 4][m0 + gr + 8]);
            }
#pragma unroll
            for (int nf = 0; nf < 8; nf++) {
                const int n0 = wn * 64 + nf * 8;
                const uint32_t b0 = __float_as_uint(Bs[kk + gc][n0 + gr]);
                const uint32_t b1 = __float_as_uint(Bs[kk + gc + 4][n0 + gr]);
                mma_tf32(acc[0][nf], afr[0], b0, b1);
                mma_tf32(acc[1][nf], afr[1], b0, b1);
            }
        }
    }

    // Epilogue: bias + feature map, direct float2 stores
    const bool fmap = (w < 2);
#pragma unroll
    for (int mf = 0; mf < 2; mf++) {
        const int mrow = bm * 128 + wm * 32 + mf * 16 + gr;
#pragma unroll
        for (int nf = 0; nf < 8; nf++) {
            const int ncol = colbase + wn * 64 + nf * 8 + 2 * gc;
            const float b0v = bias[ncol];
            const float b1v = bias[ncol + 1];
            float v0 = acc[mf][nf][0] + b0v;
            float v1 = acc[mf][nf][1] + b1v;
            float v2 = acc[mf][nf][2] + b0v;
            float v3 = acc[mf][nf][3] + b1v;
            if (fmap) {
                v0 = (v0 > 0.f) ? (v0 + 1.f) : __expf(v0);
                v1 = (v1 > 0.f) ? (v1 + 1.f) : __expf(v1);
                v2 = (v2 > 0.f) ? (v2 + 1.f) : __expf(v2);
                v3 = (v3 > 0.f) ? (v3 + 1.f) : __expf(v3);
            }
            *(float2*)&OUT[(size_t)mrow * HID + ncol]       = make_float2(v0, v1);
            *(float2*)&OUT[(size_t)(mrow + 8) * HID + ncol] = make_float2(v2, v3);
        }
    }
}

// ---------------------------------------------------------------------------
// Kernel 2: KV[n,h,m,d] = sum_s V[n,s,h,m] * K[n,s,h,d]  (+ Ksum[n,h,d])
// ---------------------------------------------------------------------------
__global__ __launch_bounds__(256) void kv_kernel()
{
    __shared__ float Vs[8][128];
    __shared__ float Ks[8][128];
    __shared__ float sKsum[128];

    const int tid = threadIdx.x;
    const int n = blockIdx.x, h = blockIdx.y;
    const size_t base = (size_t)n * F * HID + (size_t)h * D;

    const int sr = tid >> 5;
    const int c4 = (tid & 31) * 4;
    const float* vptr = g_V + base + (size_t)sr * HID + c4;
    const float* kptr = g_K + base + (size_t)sr * HID + c4;

    if (tid < 128) sKsum[tid] = 0.f;
    float ks[4] = {0.f, 0.f, 0.f, 0.f};

    const int ty = tid >> 4, tx = tid & 15;
    float acc[8][8];
#pragma unroll
    for (int i = 0; i < 8; i++)
#pragma unroll
        for (int j = 0; j < 8; j++) acc[i][j] = 0.f;

    for (int s0 = 0; s0 < F; s0 += 8) {
        float4 av = *(const float4*)(vptr + (size_t)s0 * HID);
        float4 bk = *(const float4*)(kptr + (size_t)s0 * HID);
        __syncthreads();
        *(float4*)&Vs[sr][c4] = av;
        *(float4*)&Ks[sr][c4] = bk;
        ks[0] += bk.x; ks[1] += bk.y; ks[2] += bk.z; ks[3] += bk.w;
        __syncthreads();
#pragma unroll
        for (int kk = 0; kk < 8; kk++) {
            float4 a0 = *(const float4*)&Vs[kk][ty * 4];
            float4 a1 = *(const float4*)&Vs[kk][64 + ty * 4];
            float4 b0 = *(const float4*)&Ks[kk][tx * 4];
            float4 b1 = *(const float4*)&Ks[kk][64 + tx * 4];
            float ra[8] = {a0.x, a0.y, a0.z, a0.w, a1.x, a1.y, a1.z, a1.w};
            float rb[8] = {b0.x, b0.y, b0.z, b0.w, b1.x, b1.y, b1.z, b1.w};
#pragma unroll
            for (int i = 0; i < 8; i++)
#pragma unroll
                for (int j = 0; j < 8; j++) acc[i][j] += ra[i] * rb[j];
        }
    }

    atomicAdd(&sKsum[c4 + 0], ks[0]);
    atomicAdd(&sKsum[c4 + 1], ks[1]);
    atomicAdd(&sKsum[c4 + 2], ks[2]);
    atomicAdd(&sKsum[c4 + 3], ks[3]);
    __syncthreads();

    const size_t nh = (size_t)n * H + h;
    if (tid < 128) g_Ksum[nh * D + tid] = sKsum[tid];

    const size_t kvbase = nh * D * D;
#pragma unroll
    for (int i = 0; i < 8; i++) {
        int r = (i < 4) ? (ty * 4 + i) : (64 + ty * 4 + (i - 4));   // m
        *(float4*)&g_KV[kvbase + (size_t)r * D + tx * 4] =
            make_float4(acc[i][0], acc[i][1], acc[i][2], acc[i][3]);
        *(float4*)&g_KV[kvbase + (size_t)r * D + 64 + tx * 4] =
            make_float4(acc[i][4], acc[i][5], acc[i][6], acc[i][7]);
    }
}

// ---------------------------------------------------------------------------
// Kernel 3: out[f, n, h*D+m] = Z[n,l,h] * sum_d Q[n,l,h,d] * KV[n,h,m,d]
// ---------------------------------------------------------------------------
__global__ __launch_bounds__(256) void out_kernel(float* __restrict__ out)
{
    __shared__ float Qs[8][128];
    __shared__ float KVs[8][128];
    __shared__ float sZ[128];
    __shared__ float sKs[128];

    const int tid = threadIdx.x;
    const int lt = blockIdx.x, n = blockIdx.y, h = blockIdx.z;
    const int l0 = lt * 128;
    const size_t nh = (size_t)n * H + h;
    const size_t qbase  = ((size_t)n * F + l0) * HID + (size_t)h * D;
    const size_t kvbase = nh * D * D;

    if (tid < 128) sKs[tid] = g_Ksum[nh * D + tid];
    __syncthreads();
    if (tid < 128) {
        const float* q = g_Q + qbase + (size_t)tid * HID;
        float dot = 0.f;
#pragma unroll 4
        for (int d = 0; d < D; d++) dot += q[d] * sKs[d];
        sZ[tid] = 1.f / (dot + EPSV);
    }

    const int lr  = tid >> 1;
    const int d4  = (tid & 1) * 4;
    const float* qptr  = g_Q + qbase + (size_t)lr * HID + d4;
    const float* kvptr = g_KV + kvbase + (size_t)lr * D + d4;

    const int ty = tid >> 4, tx = tid & 15;
    float acc[8][8];
#pragma unroll
    for (int i = 0; i < 8; i++)
#pragma unroll
        for (int j = 0; j < 8; j++) acc[i][j] = 0.f;

    for (int d0 = 0; d0 < D; d0 += 8) {
        float4 a = *(const float4*)(qptr + d0);
        float4 b = *(const float4*)(kvptr + d0);
        __syncthreads();
        Qs[d4 + 0][lr] = a.x; Qs[d4 + 1][lr] = a.y;
        Qs[d4 + 2][lr] = a.z; Qs[d4 + 3][lr] = a.w;
        KVs[d4 + 0][lr] = b.x; KVs[d4 + 1][lr] = b.y;
        KVs[d4 + 2][lr] = b.z; KVs[d4 + 3][lr] = b.w;
        __syncthreads();
#pragma unroll
        for (int kk = 0; kk < 8; kk++) {
            float4 a0 = *(const float4*)&Qs[kk][ty * 4];
            float4 a1 = *(const float4*)&Qs[kk][64 + ty * 4];
            float4 b0 = *(const float4*)&KVs[kk][tx * 4];
            float4 b1 = *(const float4*)&KVs[kk][64 + tx * 4];
            float ra[8] = {a0.x, a0.y, a0.z, a0.w, a1.x, a1.y, a1.z, a1.w};
            float rb[8] = {b0.x, b0.y, b0.z, b0.w, b1.x, b1.y, b1.z, b1.w};
#pragma unroll
            for (int i = 0; i < 8; i++)
#pragma unroll
                for (int j = 0; j < 8; j++) acc[i][j] += ra[i] * rb[j];
        }
    }

#pragma unroll
    for (int i = 0; i < 8; i++) {
        int r = (i < 4) ? (ty * 4 + i) : (64 + ty * 4 + (i - 4));   // l within tile
        float z = sZ[r];
        size_t obase = (size_t)(l0 + r) * (NJ * HID) + (size_t)n * HID + (size_t)h * D;
        *(float4*)&out[obase + tx * 4] =
            make_float4(acc[i][0] * z, acc[i][1] * z, acc[i][2] * z, acc[i][3] * z);
        *(float4*)&out[obase + 64 + tx * 4] =
            make_float4(acc[i][4] * z, acc[i][5] * z, acc[i][6] * z, acc[i][7] * z);
    }
}

// ---------------------------------------------------------------------------
extern "C" void kernel_launch(void* const* d_in, const int* in_sizes, int n_in,
                              void* d_out, int out_size)
{
    const float* x  = (const float*)d_in[0];
    const float* Wq = (const float*)d_in[1];
    const float* bq = (const float*)d_in[2];
    const float* Wk = (const float*)d_in[3];
    const float* bk = (const float*)d_in[4];
    const float* Wv = (const float*)d_in[5];
    const float* bv = (const float*)d_in[6];
    float* out = (float*)d_out;

    dim3 g1(M_TOT / 128, 24);            // 512 x 24
    qkv_mma_kernel<<<g1, 256>>>(x, Wq, bq, Wk, bk, Wv, bv);

    dim3 g2(NJ, H);                      // 64 x 8
    kv_kernel<<<g2, 256>>>();

    dim3 g3(F / 128, NJ, H);             // 8 x 64 x 8
    out_kernel<<<g3, 256>>>(out);
}

// round 3
// speedup vs baseline: 2.3655x; 1.4111x over previous
#include <cuda_runtime.h>
#include <math.h>
#include <stdint.h>

#define F    1024
#define NJ   64
#define C    256
#define HID  1024
#define H    8
#define D    128
#define M_TOT (NJ * F)      // 65536
#define EPSV 1e-6f

// Scratch (device globals — no allocation allowed in kernel_launch)
__device__ float g_Q[(size_t)M_TOT * HID];   // feature-mapped Q  (n, f, hid)
__device__ float g_K[(size_t)M_TOT * HID];   // feature-mapped K
__device__ float g_V[(size_t)M_TOT * HID];   // V
__device__ float g_KV[(size_t)NJ * H * D * D];   // KV[n,h,m,d]
__device__ float g_Ksum[(size_t)NJ * H * D];     // Ksum[n,h,d]

__device__ __forceinline__ float ftf32(float x) {
    float r;
    asm("cvt.rna.tf32.f32 %0, %1;" : "=f"(r) : "f"(x));
    return r;
}

__device__ __forceinline__ void mma_tf32(float* c, const uint32_t* a,
                                         uint32_t b0, uint32_t b1) {
    asm volatile(
        "mma.sync.aligned.m16n8k8.row.col.f32.tf32.tf32.f32 "
        "{%0,%1,%2,%3}, {%4,%5,%6,%7}, {%8,%9}, {%0,%1,%2,%3};"
        : "+f"(c[0]), "+f"(c[1]), "+f"(c[2]), "+f"(c[3])
        : "r"(a[0]), "r"(a[1]), "r"(a[2]), "r"(a[3]), "r"(b0), "r"(b1));
}

// Shared mma inner block: As/Bs are [32][136] k-major tiles.
// 8 warps: wm=warp&3 (m offset 32), wn=warp>>2 (n offset 64).
#define MMA_TILE_BODY(As, Bs, acc)                                            \
    _Pragma("unroll")                                                         \
    for (int ks = 0; ks < 4; ks++) {                                          \
        const int kk = ks * 8;                                                \
        uint32_t afr[2][4];                                                   \
        _Pragma("unroll")                                                     \
        for (int mf = 0; mf < 2; mf++) {                                      \
            const int m0 = wm * 32 + mf * 16;                                 \
            afr[mf][0] = __float_as_uint(As[kk + gc][m0 + gr]);               \
            afr[mf][1] = __float_as_uint(As[kk + gc][m0 + gr + 8]);           \
            afr[mf][2] = __float_as_uint(As[kk + gc + 4][m0 + gr]);           \
            afr[mf][3] = __float_as_uint(As[kk + gc + 4][m0 + gr + 8]);       \
        }                                                                     \
        _Pragma("unroll")                                                     \
        for (int nf = 0; nf < 8; nf++) {                                      \
            const int n0 = wn * 64 + nf * 8;                                  \
            const uint32_t b0 = __float_as_uint(Bs[kk + gc][n0 + gr]);        \
            const uint32_t b1 = __float_as_uint(Bs[kk + gc + 4][n0 + gr]);    \
            mma_tf32(acc[0][nf], afr[0], b0, b1);                             \
            mma_tf32(acc[1][nf], afr[1], b0, b1);                             \
        }                                                                     \
    }

// ---------------------------------------------------------------------------
// Kernel 1: fused QKV projection on tensor cores (tf32 mma.sync)
// ---------------------------------------------------------------------------
__global__ __launch_bounds__(256) void qkv_mma_kernel(
    const float* __restrict__ x,
    const float* __restrict__ Wq, const float* __restrict__ bq,
    const float* __restrict__ Wk, const float* __restrict__ bk,
    const float* __restrict__ Wv, const float* __restrict__ bv)
{
    __shared__ float As[32][136];   // [k][m]
    __shared__ float Bs[32][136];   // [k][n]

    const int tid  = threadIdx.x;
    const int lane = tid & 31;
    const int warp = tid >> 5;
    const int wm   = warp & 3;
    const int wn   = warp >> 2;
    const int gr   = lane >> 2;
    const int gc   = lane & 3;

    const int bm = blockIdx.x;      // 0..511
    const int bn = blockIdx.y;      // 0..23
    const int w  = bn >> 3;         // 0=Q,1=K,2=V
    const float* Wp   = (w == 0) ? Wq : ((w == 1) ? Wk : Wv);
    const float* bias = (w == 0) ? bq : ((w == 1) ? bk : bv);
    float* OUT        = (w == 0) ? g_Q : ((w == 1) ? g_K : g_V);
    const int colbase = (bn & 7) * 128;

    const int ar   = tid >> 1;
    const int am   = bm * 128 + ar;
    const int fidx = am & (F - 1);
    const int nidx = am >> 10;
    const float* aptr = x + (size_t)fidx * (NJ * C) + (size_t)nidx * C + (tid & 1) * 16;

    const int bkr = tid >> 3;
    const int bco = (tid & 7) * 4;
    const float* bptr = Wp + (size_t)bkr * HID + colbase + bco;

    float acc[2][8][4];
#pragma unroll
    for (int mf = 0; mf < 2; mf++)
#pragma unroll
        for (int nf = 0; nf < 8; nf++)
#pragma unroll
            for (int i = 0; i < 4; i++) acc[mf][nf][i] = 0.f;

    for (int kt = 0; kt < 8; kt++) {
        const int k0 = kt * 32;
        float4 aR[4], bR[4];
#pragma unroll
        for (int i = 0; i < 4; i++) aR[i] = *(const float4*)(aptr + k0 + i * 4);
#pragma unroll
        for (int i = 0; i < 4; i++) bR[i] = *(const float4*)(bptr + (size_t)k0 * HID + i * 32);

        __syncthreads();
#pragma unroll
        for (int i = 0; i < 4; i++) {
            const int kb = (tid & 1) * 16 + i * 4;
            As[kb + 0][ar] = ftf32(aR[i].x);
            As[kb + 1][ar] = ftf32(aR[i].y);
            As[kb + 2][ar] = ftf32(aR[i].z);
            As[kb + 3][ar] = ftf32(aR[i].w);
        }
#pragma unroll
        for (int i = 0; i < 4; i++) {
            float4 t = bR[i];
            t.x = ftf32(t.x); t.y = ftf32(t.y); t.z = ftf32(t.z); t.w = ftf32(t.w);
            *(float4*)&Bs[bkr][bco + i * 32] = t;
        }
        __syncthreads();

        MMA_TILE_BODY(As, Bs, acc)
    }

    const bool fmap = (w < 2);
#pragma unroll
    for (int mf = 0; mf < 2; mf++) {
        const int mrow = bm * 128 + wm * 32 + mf * 16 + gr;
#pragma unroll
        for (int nf = 0; nf < 8; nf++) {
            const int ncol = colbase + wn * 64 + nf * 8 + 2 * gc;
            const float b0v = bias[ncol];
            const float b1v = bias[ncol + 1];
            float v0 = acc[mf][nf][0] + b0v;
            float v1 = acc[mf][nf][1] + b1v;
            float v2 = acc[mf][nf][2] + b0v;
            float v3 = acc[mf][nf][3] + b1v;
            if (fmap) {
                v0 = (v0 > 0.f) ? (v0 + 1.f) : __expf(v0);
                v1 = (v1 > 0.f) ? (v1 + 1.f) : __expf(v1);
                v2 = (v2 > 0.f) ? (v2 + 1.f) : __expf(v2);
                v3 = (v3 > 0.f) ? (v3 + 1.f) : __expf(v3);
            }
            *(float2*)&OUT[(size_t)mrow * HID + ncol]       = make_float2(v0, v1);
            *(float2*)&OUT[(size_t)(mrow + 8) * HID + ncol] = make_float2(v2, v3);
        }
    }
}

// ---------------------------------------------------------------------------
// Kernel 2 (mma): KV[n,h,m,d] = sum_s V[n,s,h,m] * K[n,s,h,d]  + Ksum
// A = V^T (As[s][m]), B = K^T (Bs[s][d]); both row-contiguous loads.
// ---------------------------------------------------------------------------
__global__ __launch_bounds__(256) void kv_mma_kernel()
{
    __shared__ float As[32][136];   // [s][m] (V)
    __shared__ float Bs[32][136];   // [s][d] (K)
    __shared__ float sKsum[128];

    const int tid  = threadIdx.x;
    const int lane = tid & 31;
    const int warp = tid >> 5;
    const int wm   = warp & 3;
    const int wn   = warp >> 2;
    const int gr   = lane >> 2;
    const int gc   = lane & 3;

    const int n = blockIdx.x, h = blockIdx.y;
    const size_t base = (size_t)n * F * HID + (size_t)h * D;

    const int sr = tid >> 3;          // 0..31 (s within tile)
    const int c0 = (tid & 7) * 4;     // column base
    const float* vptr = g_V + base + (size_t)sr * HID + c0;
    const float* kptr = g_K + base + (size_t)sr * HID + c0;

    if (tid < 128) sKsum[tid] = 0.f;
    float4 kacc[4];
#pragma unroll
    for (int i = 0; i < 4; i++) kacc[i] = make_float4(0.f, 0.f, 0.f, 0.f);

    float acc[2][8][4];
#pragma unroll
    for (int mf = 0; mf < 2; mf++)
#pragma unroll
        for (int nf = 0; nf < 8; nf++)
#pragma unroll
            for (int i = 0; i < 4; i++) acc[mf][nf][i] = 0.f;

    for (int s0 = 0; s0 < F; s0 += 32) {
        float4 av[4], ak[4];
#pragma unroll
        for (int i = 0; i < 4; i++) {
            av[i] = *(const float4*)(vptr + (size_t)s0 * HID + i * 32);
            ak[i] = *(const float4*)(kptr + (size_t)s0 * HID + i * 32);
        }
        __syncthreads();
#pragma unroll
        for (int i = 0; i < 4; i++) {
            float4 tv = av[i], tk = ak[i];
            kacc[i].x += tk.x; kacc[i].y += tk.y; kacc[i].z += tk.z; kacc[i].w += tk.w;
            tv.x = ftf32(tv.x); tv.y = ftf32(tv.y); tv.z = ftf32(tv.z); tv.w = ftf32(tv.w);
            tk.x = ftf32(tk.x); tk.y = ftf32(tk.y); tk.z = ftf32(tk.z); tk.w = ftf32(tk.w);
            *(float4*)&As[sr][c0 + i * 32] = tv;
            *(float4*)&Bs[sr][c0 + i * 32] = tk;
        }
        __syncthreads();

        MMA_TILE_BODY(As, Bs, acc)
    }

#pragma unroll
    for (int i = 0; i < 4; i++) {
        atomicAdd(&sKsum[c0 + i * 32 + 0], kacc[i].x);
        atomicAdd(&sKsum[c0 + i * 32 + 1], kacc[i].y);
        atomicAdd(&sKsum[c0 + i * 32 + 2], kacc[i].z);
        atomicAdd(&sKsum[c0 + i * 32 + 3], kacc[i].w);
    }
    __syncthreads();

    const size_t nh = (size_t)n * H + h;
    if (tid < 128) g_Ksum[nh * D + tid] = sKsum[tid];

    const size_t kvbase = nh * D * D;
#pragma unroll
    for (int mf = 0; mf < 2; mf++) {
        const int mrow = wm * 32 + mf * 16 + gr;
#pragma unroll
        for (int nf = 0; nf < 8; nf++) {
            const int ncol = wn * 64 + nf * 8 + 2 * gc;
            *(float2*)&g_KV[kvbase + (size_t)mrow * D + ncol] =
                make_float2(acc[mf][nf][0], acc[mf][nf][1]);
            *(float2*)&g_KV[kvbase + (size_t)(mrow + 8) * D + ncol] =
                make_float2(acc[mf][nf][2], acc[mf][nf][3]);
        }
    }
}

// ---------------------------------------------------------------------------
// Kernel 3 (mma): out[l, n, h*D+m] = Z[l] * sum_d Q[l,d] * KV[m,d]
// A = Q^T (As[d][l]), B = KV^T (Bs[d][m]); K = 128 (4 tiles).
// ---------------------------------------------------------------------------
__global__ __launch_bounds__(256) void out_mma_kernel(float* __restrict__ out)
{
    __shared__ float As[32][136];   // [d][l]
    __shared__ float Bs[32][136];   // [d][m]
    __shared__ float sZ[128];
    __shared__ float sKs[128];

    const int tid  = threadIdx.x;
    const int lane = tid & 31;
    const int warp = tid >> 5;
    const int wm   = warp & 3;
    const int wn   = warp >> 2;
    const int gr   = lane >> 2;
    const int gc   = lane & 3;

    const int lt = blockIdx.x, n = blockIdx.y, h = blockIdx.z;
    const int l0 = lt * 128;
    const size_t nh = (size_t)n * H + h;
    const size_t qbase  = ((size_t)n * F + l0) * HID + (size_t)h * D;
    const size_t kvbase = nh * D * D;

    if (tid < 128) sKs[tid] = g_Ksum[nh * D + tid];
    __syncthreads();

    // Z: one warp per row, coalesced float4 + shfl reduce. 16 rows/warp.
    {
        float4 kv4 = *(const float4*)&sKs[lane * 4];
#pragma unroll
        for (int r8 = 0; r8 < 16; r8++) {
            const int row = warp * 16 + r8;
            const float* q = g_Q + qbase + (size_t)row * HID;
            float4 qv = *(const float4*)(q + lane * 4);
            float d = qv.x * kv4.x + qv.y * kv4.y + qv.z * kv4.z + qv.w * kv4.w;
#pragma unroll
            for (int off = 16; off; off >>= 1) d += __shfl_xor_sync(0xffffffffu, d, off);
            if (lane == 0) sZ[row] = 1.f / (d + EPSV);
        }
    }

    const int lr  = tid >> 1;
    const int d16 = (tid & 1) * 16;
    const float* qp  = g_Q + qbase + (size_t)lr * HID + d16;
    const float* kvp = g_KV + kvbase + (size_t)lr * D + d16;

    float acc[2][8][4];
#pragma unroll
    for (int mf = 0; mf < 2; mf++)
#pragma unroll
        for (int nf = 0; nf < 8; nf++)
#pragma unroll
            for (int i = 0; i < 4; i++) acc[mf][nf][i] = 0.f;

    for (int d0 = 0; d0 < D; d0 += 32) {
        float4 aR[4], bR[4];
#pragma unroll
        for (int i = 0; i < 4; i++) {
            aR[i] = *(const float4*)(qp + d0 + i * 4);
            bR[i] = *(const float4*)(kvp + d0 + i * 4);
        }
        __syncthreads();
#pragma unroll
        for (int i = 0; i < 4; i++) {
            const int kb = d16 + i * 4;
            As[kb + 0][lr] = ftf32(aR[i].x);
            As[kb + 1][lr] = ftf32(aR[i].y);
            As[kb + 2][lr] = ftf32(aR[i].z);
            As[kb + 3][lr] = ftf32(aR[i].w);
            Bs[kb + 0][lr] = ftf32(bR[i].x);
            Bs[kb + 1][lr] = ftf32(bR[i].y);
            Bs[kb + 2][lr] = ftf32(bR[i].z);
            Bs[kb + 3][lr] = ftf32(bR[i].w);
        }
        __syncthreads();

        MMA_TILE_BODY(As, Bs, acc)
    }

#pragma unroll
    for (int mf = 0; mf < 2; mf++) {
        const int row = wm * 32 + mf * 16 + gr;     // l within tile
        const float z0 = sZ[row];
        const float z1 = sZ[row + 8];
        const size_t ob0 = (size_t)(l0 + row) * (NJ * HID) + (size_t)n * HID + (size_t)h * D;
        const size_t ob1 = (size_t)(l0 + row + 8) * (NJ * HID) + (size_t)n * HID + (size_t)h * D;
#pragma unroll
        for (int nf = 0; nf < 8; nf++) {
            const int ncol = wn * 64 + nf * 8 + 2 * gc;
            *(float2*)&out[ob0 + ncol] =
                make_float2(acc[mf][nf][0] * z0, acc[mf][nf][1] * z0);
            *(float2*)&out[ob1 + ncol] =
                make_float2(acc[mf][nf][2] * z1, acc[mf][nf][3] * z1);
        }
    }
}

// ---------------------------------------------------------------------------
extern "C" void kernel_launch(void* const* d_in, const int* in_sizes, int n_in,
                              void* d_out, int out_size)
{
    const float* x  = (const float*)d_in[0];
    const float* Wq = (const float*)d_in[1];
    const float* bq = (const float*)d_in[2];
    const float* Wk = (const float*)d_in[3];
    const float* bk = (const float*)d_in[4];
    const float* Wv = (const float*)d_in[5];
    const float* bv = (const float*)d_in[6];
    float* out = (float*)d_out;

    dim3 g1(M_TOT / 128, 24);            // 512 x 24
    qkv_mma_kernel<<<g1, 256>>>(x, Wq, bq, Wk, bk, Wv, bv);

    dim3 g2(NJ, H);                      // 64 x 8
    kv_mma_kernel<<<g2, 256>>>();

    dim3 g3(F / 128, NJ, H);             // 8 x 64 x 8
    out_mma_kernel<<<g3, 256>>>(out);
}